// round 12
// baseline (speedup 1.0000x reference)
#include <cuda_runtime.h>
#include <cstdint>

#define S_LEN  128
#define B_SZ   32
#define E2D    1024
#define DHID   512
#define AHID   32
#define EMBD   256
#define VOCAB  32000
#define CATD   1536   // DH + E2  (W1 row length)
#define XDIM   1280   // E2 + EMB (W_ih row length)
#define NSPI   10     // K-splits for gi (1280/128)
#define NSPH   4      // K-splits for gh (512/128)

// estep grid roles
#define NLOG   125    // logits blocks (256 vocab each)
#define NGH    48
#define NATTN  32
#define NBLK   (NLOG + NGH + NATTN)   // 205

// logits smem layout (floats)
#define LW_STRIDE 36
#define LW_BUF    (256 * LW_STRIDE)   // 9216 floats per Wo buffer
#define LH_BUF    (32 * LW_STRIDE)    // 1152 floats per h buffer
#define LOG_SMEM_FLOATS (2 * LW_BUF + 2 * LH_BUF)   // 20736 floats = 82944 B

// ---------------- device scratch (no allocation allowed) --------------------
__device__ __align__(16) float g_enc_proj[S_LEN * B_SZ * AHID]; // W1_enc@enc + b1
__device__ __align__(16) float g_h[B_SZ * DHID];                // hidden state
__device__ __align__(16) float g_ctx[B_SZ * E2D];               // attention context
__device__ __align__(16) float g_gip[NSPI * 3 * DHID * B_SZ];   // gi partials [sp][o][b]
__device__ __align__(16) float g_ghp[NSPH * 3 * DHID * B_SZ];   // gh partials [c][o][b]
__device__ unsigned long long g_amax[B_SZ];

// ---------------- helpers ---------------------------------------------------
__device__ __forceinline__ unsigned int fkey(float v) {
    unsigned int u = __float_as_uint(v);
    return (u & 0x80000000u) ? ~u : (u | 0x80000000u);
}
// larger value wins; on equal value LOWER index wins (jnp.argmax semantics)
__device__ __forceinline__ unsigned long long packkey(float v, int idx) {
    return ((unsigned long long)fkey(v) << 32) |
           (unsigned long long)(0x7FFFFFFFu - (unsigned int)idx);
}
__device__ __forceinline__ void ffma2(unsigned long long& d, unsigned long long a,
                                      unsigned long long b) {
    asm("fma.rn.f32x2 %0, %1, %2, %0;" : "+l"(d) : "l"(a), "l"(b));
}
__device__ __forceinline__ float fcollapse(unsigned long long v) {
    float lo, hi;
    asm("mov.b64 {%0, %1}, %2;" : "=f"(lo), "=f"(hi) : "l"(v));
    return lo + hi;
}
__device__ __forceinline__ unsigned long long mk_policy_el() {
    unsigned long long pol;
    asm("createpolicy.fractional.L2::evict_last.b64 %0, 1.0;" : "=l"(pol));
    return pol;
}
__device__ __forceinline__ void cpa16p(void* smem_dst, const void* gsrc,
                                       unsigned long long pol) {
    unsigned sd = (unsigned)__cvta_generic_to_shared(smem_dst);
    asm volatile("cp.async.cg.shared.global.L2::cache_hint [%0], [%1], 16, %2;"
                 :: "r"(sd), "l"(gsrc), "l"(pol));
}
__device__ __forceinline__ void cpa_commit() {
    asm volatile("cp.async.commit_group;" ::: "memory");
}
__device__ __forceinline__ void cpa_wait0() {
    asm volatile("cp.async.wait_group 0;" ::: "memory");
}
// weight loads that should stay resident in L2 (cache_hint form: any width OK)
__device__ __forceinline__ float ldg_el(const float* p, unsigned long long pol) {
    float v;
    asm("ld.global.nc.L2::cache_hint.f32 %0, [%1], %2;"
        : "=f"(v) : "l"(p), "l"(pol));
    return v;
}
__device__ __forceinline__ float4 ldg_el4(const float4* p, unsigned long long pol) {
    float4 v;
    asm("ld.global.nc.L2::cache_hint.v4.f32 {%0,%1,%2,%3}, [%4], %5;"
        : "=f"(v.x), "=f"(v.y), "=f"(v.z), "=f"(v.w) : "l"(p), "l"(pol));
    return v;
}

// ---------------- init: h=0, amax encodes sos token -------------------------
__global__ void k_init(const int* __restrict__ sos_p) {
    int i = blockIdx.x * blockDim.x + threadIdx.x;
    if (i < B_SZ * DHID) g_h[i] = 0.0f;
    if (i < B_SZ) {
        int sos = *sos_p;
        g_amax[i] = (unsigned long long)(0x7FFFFFFFu - (unsigned int)sos);
    }
}

// ---------------- one-time: enc_proj[sb][a] = W1[a,512:]@enc[sb] + b1[a] ----
__global__ void k_encproj(const float* __restrict__ enc,
                          const float* __restrict__ W1,
                          const float* __restrict__ b1) {
    __shared__ float enc_sh[8 * E2D];
    int tid = threadIdx.x;
    int sb0 = blockIdx.x * 8;
    for (int i = tid; i < 8 * E2D; i += 256)
        enc_sh[i] = enc[sb0 * E2D + i];
    __syncthreads();
    int a = tid & 31;
    int r = tid >> 5;
    const float* w = W1 + a * CATD + DHID;
    const float* e = enc_sh + r * E2D;
    float a0 = 0.f, a1 = 0.f, a2 = 0.f, a3 = 0.f;
#pragma unroll 8
    for (int k = 0; k < E2D; k += 4) {
        a0 = fmaf(w[k],     e[k],     a0);
        a1 = fmaf(w[k + 1], e[k + 1], a1);
        a2 = fmaf(w[k + 2], e[k + 2], a2);
        a3 = fmaf(w[k + 3], e[k + 3], a3);
    }
    g_enc_proj[(sb0 + r) * AHID + a] = a0 + a1 + a2 + a3 + b1[a];
}

// =============================================================================
// k_estep: 205 blocks x 256 threads, one balanced wave:
//   blocks [0,125)    : logits 256v x 32b + fused argmax (f32x2 over k-pairs)
//   blocks [125,173)  : gh partial GEMM for NEXT step (128 threads active)
//   blocks [173,205)  : attention + context for NEXT step (128 threads active)
// =============================================================================
extern __shared__ float sm[];
__global__ void __launch_bounds__(256) k_estep(
    const float* __restrict__ enc,
    const float* __restrict__ W1,
    const float* __restrict__ W2,
    const float* __restrict__ b2,
    const float* __restrict__ W_hh,
    const float* __restrict__ Wo,
    const float* __restrict__ bo,
    float* __restrict__ out_t) {
    __shared__ unsigned long long bmax[B_SZ];
    int tid = threadIdx.x;
    int bk = blockIdx.x;
    unsigned long long pol = mk_policy_el();

    if (bk < NLOG) {
        // ---- logits: D[b][v] = h[b] . Wo[v] + bo[v] ------------------------
        if (out_t == nullptr) return;
        int v0 = bk * 256;
        float* wo_s = sm;
        float* h_s  = sm + 2 * LW_BUF;
        int w  = tid >> 5;
        int tx = tid & 31;
        int vg = w & 3;                          // v quarter (64)
        int bg = w >> 2;                         // b half (16)
        int vsub = tx >> 2;                      // 0..7
        int bsub = tx & 3;                       // 0..3
        if (tid < B_SZ) bmax[tid] = 0ull;

        unsigned long long acc[8][4];
#pragma unroll
        for (int j = 0; j < 8; j++)
#pragma unroll
            for (int m = 0; m < 4; m++) acc[j][m] = 0ull;

        // prefetch chunk 0 (k in [0,32))
        {
#pragma unroll
            for (int j = 0; j < 8; j++) {
                int gid = tid + 256 * j;          // 2048 granules: v 0..255, g16 0..7
                int v = gid >> 3, g16 = gid & 7;
                cpa16p(wo_s + v * LW_STRIDE + g16 * 4,
                       Wo + (size_t)(v0 + v) * DHID + g16 * 4, pol);
            }
            {
                int b = tid >> 3, g16 = tid & 7;  // 256 granules
                cpa16p(h_s + b * LW_STRIDE + g16 * 4,
                       g_h + b * DHID + g16 * 4, pol);
            }
            cpa_commit();
        }

        for (int c = 0; c < 16; c++) {
            cpa_wait0();
            __syncthreads();
            if (c < 15) {
                int kc = (c + 1) * 32;
                float* wd = wo_s + ((c + 1) & 1) * LW_BUF;
                float* hd = h_s + ((c + 1) & 1) * LH_BUF;
#pragma unroll
                for (int j = 0; j < 8; j++) {
                    int gid = tid + 256 * j;
                    int v = gid >> 3, g16 = gid & 7;
                    cpa16p(wd + v * LW_STRIDE + g16 * 4,
                           Wo + (size_t)(v0 + v) * DHID + kc + g16 * 4, pol);
                }
                {
                    int b = tid >> 3, g16 = tid & 7;
                    cpa16p(hd + b * LW_STRIDE + g16 * 4,
                           g_h + b * DHID + kc + g16 * 4, pol);
                }
                cpa_commit();
            }
            const float* wb = wo_s + (c & 1) * LW_BUF
                              + (vg * 64 + vsub) * LW_STRIDE;
            const float* hb = h_s + (c & 1) * LH_BUF
                              + (bg * 16 + bsub) * LW_STRIDE;
#pragma unroll
            for (int g = 0; g < 8; g++) {       // 4 k per group (2 f32x2 pairs)
                ulonglong2 wq[8];
#pragma unroll
                for (int j = 0; j < 8; j++)
                    wq[j] = *reinterpret_cast<const ulonglong2*>(
                        wb + j * 8 * LW_STRIDE + g * 4);
                ulonglong2 hq[4];
#pragma unroll
                for (int m = 0; m < 4; m++)
                    hq[m] = *reinterpret_cast<const ulonglong2*>(
                        hb + m * 4 * LW_STRIDE + g * 4);
#pragma unroll
                for (int j = 0; j < 8; j++)
#pragma unroll
                    for (int m = 0; m < 4; m++) {
                        ffma2(acc[j][m], wq[j].x, hq[m].x);
                        ffma2(acc[j][m], wq[j].y, hq[m].y);
                    }
            }
        }

        // stage results: st[b][v] with q-padded layout (row 264, 33 per 32-v)
        __syncthreads();
        float* st = sm;
#pragma unroll
        for (int j = 0; j < 8; j++) {
            int v = vg * 64 + vsub + 8 * j;
            int q = v >> 5, i = v & 31;
#pragma unroll
            for (int m = 0; m < 4; m++) {
                int b = bg * 16 + bsub + 4 * m;
                st[b * 264 + q * 33 + i] = fcollapse(acc[j][m]);
            }
        }
        __syncthreads();

        // coalesced write-out + argmax: thread handles 32 consecutive v of row b
        {
            int b = tid >> 3, q = tid & 7;
            int vbase = v0 + q * 32;
            const float* srow = st + b * 264 + q * 33;
            float best = -3.4e38f; int bi = 0;
            float vals[32];
#pragma unroll
            for (int i = 0; i < 32; i++) {
                float x = srow[i] + bo[vbase + i];
                vals[i] = x;
                if (x > best) { best = x; bi = vbase + i; }
            }
            float* orow = out_t + (size_t)b * VOCAB + vbase;
#pragma unroll
            for (int i = 0; i < 8; i++) {
                float4 v4 = make_float4(vals[4 * i], vals[4 * i + 1],
                                        vals[4 * i + 2], vals[4 * i + 3]);
                __stcs(reinterpret_cast<float4*>(orow + 4 * i), v4);
            }
            atomicMax(&bmax[b], packkey(best, bi));
        }
        __syncthreads();
        if (tid < B_SZ) atomicMax(&g_amax[tid], bmax[tid]);
        return;
    }

    if (bk < NLOG + NGH) {
        // ---- gh partial: tile 128o x 32b, K range [c*128, c*128+128) -------
        if (tid >= 128) return;
        int r = bk - NLOG;
        int c = r & 3, ot = r >> 2;
        int o0 = ot * 128, kc0 = c * 128;
        float* w_s = sm;              // [k][o] stride 129 (4128 floats)
        float* x_s = sm + 4128;       // [k][b] stride 33
        int tk = tid & 31, tg = tid >> 5;
        int tx = tid & 31, ty = tid >> 5;
        float acc[4][8] = {};
        float pw[32], ph[8];
#pragma unroll
        for (int j = 0; j < 32; j++)
            pw[j] = ldg_el(W_hh + (o0 + tg + 4 * j) * DHID + kc0 + tk, pol);
#pragma unroll
        for (int j = 0; j < 8; j++)
            ph[j] = g_h[(tg + 4 * j) * DHID + kc0 + tk];
        for (int kc = kc0; kc < kc0 + 128; kc += 32) {
            __syncthreads();
#pragma unroll
            for (int j = 0; j < 32; j++) w_s[tk * 129 + tg + 4 * j] = pw[j];
#pragma unroll
            for (int j = 0; j < 8; j++)  x_s[tk * 33 + tg + 4 * j] = ph[j];
            __syncthreads();
            if (kc + 32 < kc0 + 128) {
#pragma unroll
                for (int j = 0; j < 32; j++)
                    pw[j] = ldg_el(W_hh + (o0 + tg + 4 * j) * DHID + kc + 32 + tk, pol);
#pragma unroll
                for (int j = 0; j < 8; j++)
                    ph[j] = g_h[(tg + 4 * j) * DHID + kc + 32 + tk];
            }
#pragma unroll 4
            for (int k = 0; k < 32; k++) {
                const float* wr = &w_s[k * 129 + tx];
                float w0 = wr[0], w1 = wr[32], w2 = wr[64], w3 = wr[96];
                const float* hr = &x_s[k * 33 + ty * 8];
#pragma unroll
                for (int bj = 0; bj < 8; bj++) {
                    float hb = hr[bj];
                    acc[0][bj] = fmaf(w0, hb, acc[0][bj]);
                    acc[1][bj] = fmaf(w1, hb, acc[1][bj]);
                    acc[2][bj] = fmaf(w2, hb, acc[2][bj]);
                    acc[3][bj] = fmaf(w3, hb, acc[3][bj]);
                }
            }
        }
#pragma unroll
        for (int vi = 0; vi < 4; vi++)
#pragma unroll
            for (int bj = 0; bj < 8; bj++)
                g_ghp[(c * 3 * DHID + o0 + tx + vi * 32) * B_SZ + ty * 8 + bj] = acc[vi][bj];
        return;
    }

    // ---- attention for next step, one block per batch ----------------------
    {
        if (tid >= 128) return;
        int b = bk - (NLOG + NGH);
        float* h_sh  = sm;         // 512
        float* part  = sm + 512;   // 4*32
        float* hproj = sm + 640;   // 32
        float* sc    = sm + 672;   // 128
        float* red   = sm + 800;   // 2
        for (int i = tid; i < DHID; i += 128) h_sh[i] = g_h[b * DHID + i];
        __syncthreads();
        {   // hproj[a] = W1[a,0:512] @ h : 4 segments of 128
            int a = tid & 31, seg = tid >> 5;
            const float* w  = W1 + a * CATD + seg * 128;
            const float* hh = h_sh + seg * 128;
            float acc = 0.f;
#pragma unroll 8
            for (int k = 0; k < 128; k++) acc = fmaf(w[k], hh[k], acc);
            part[seg * 32 + a] = acc;
        }
        __syncthreads();
        if (tid < AHID)
            hproj[tid] = part[tid] + part[32 + tid] + part[64 + tid] + part[96 + tid];
        __syncthreads();
        {   // scores over S (one thread per s)
            int s = tid;
            const float* ep = g_enc_proj + (s * B_SZ + b) * AHID;
            float sv = b2[0];
#pragma unroll
            for (int a = 0; a < AHID; a++) {
                float t = ep[a] + hproj[a];
                sv = fmaf(W2[a], fmaxf(t, 0.f), sv);
            }
            sc[s] = sv;
        }
        __syncthreads();
        if (tid < 32) {
            float m = fmaxf(fmaxf(sc[tid], sc[tid + 32]), fmaxf(sc[tid + 64], sc[tid + 96]));
#pragma unroll
            for (int off = 16; off > 0; off >>= 1)
                m = fmaxf(m, __shfl_xor_sync(0xffffffffu, m, off));
            if (tid == 0) red[0] = m;
        }
        __syncthreads();
        sc[tid] = expf(sc[tid] - red[0]);
        __syncthreads();
        if (tid < 32) {
            float s4 = sc[tid] + sc[tid + 32] + sc[tid + 64] + sc[tid + 96];
#pragma unroll
            for (int off = 16; off > 0; off >>= 1)
                s4 += __shfl_xor_sync(0xffffffffu, s4, off);
            if (tid == 0) red[1] = 1.0f / s4;
        }
        __syncthreads();
        sc[tid] *= red[1];
        __syncthreads();
        {   // context: each thread 8 consecutive e, enc kept L2-resident
            float acc[8] = {};
            const float4* e4 = reinterpret_cast<const float4*>(enc);
#pragma unroll 4
            for (int s = 0; s < S_LEN; s++) {
                float a = sc[s];
                int base4 = ((s * B_SZ + b) * E2D + tid * 8) >> 2;
                float4 v0 = ldg_el4(e4 + base4, pol);
                float4 v1 = ldg_el4(e4 + base4 + 1, pol);
                acc[0] = fmaf(a, v0.x, acc[0]); acc[1] = fmaf(a, v0.y, acc[1]);
                acc[2] = fmaf(a, v0.z, acc[2]); acc[3] = fmaf(a, v0.w, acc[3]);
                acc[4] = fmaf(a, v1.x, acc[4]); acc[5] = fmaf(a, v1.y, acc[5]);
                acc[6] = fmaf(a, v1.z, acc[6]); acc[7] = fmaf(a, v1.w, acc[7]);
            }
            float* dst = g_ctx + b * E2D + tid * 8;
#pragma unroll
            for (int j = 0; j < 8; j++) dst[j] = acc[j];
        }
    }
}

// ---------------- gi partial GEMM (x = [ctx | emb[argmax]]) -----------------
// grid 240 blocks (24 o-tiles of 64 x 10 K-splits), 128 threads
__global__ void __launch_bounds__(128) k_gigemm(const float* __restrict__ W_ih,
                                                const float* __restrict__ emb) {
    __shared__ __align__(16) float w_s[32 * 65];
    __shared__ float x_s[32 * 33];
    __shared__ int sh_id[B_SZ];
    int tid = threadIdx.x;
    unsigned long long pol = mk_policy_el();
    int ot = blockIdx.x % 24, sp = blockIdx.x / 24;
    int o0 = ot * 64, kc0 = sp * 128;
    int tk = tid & 31, tg = tid >> 5;
    if (tid < B_SZ) {
        unsigned long long p = g_amax[tid];
        sh_id[tid] = (int)(0x7FFFFFFFu - (unsigned int)(p & 0x7FFFFFFFull));
    }
    __syncthreads();
    int tx = tid & 31, ty = tid >> 5;
    bool is_ctx = (kc0 < E2D);
    float acc[2][8] = {};
    float pw[16], px[8];
#pragma unroll
    for (int j = 0; j < 16; j++)
        pw[j] = ldg_el(W_ih + (o0 + tg + 4 * j) * XDIM + kc0 + tk, pol);
#pragma unroll
    for (int j = 0; j < 8; j++) {
        int b = tg + 4 * j, kg = kc0 + tk;
        px[j] = is_ctx ? g_ctx[b * E2D + kg]
                       : ldg_el(emb + (size_t)sh_id[b] * EMBD + (kg - E2D), pol);
    }
    for (int kc = kc0; kc < kc0 + 128; kc += 32) {
        __syncthreads();
#pragma unroll
        for (int j = 0; j < 16; j++) w_s[tk * 65 + tg + 4 * j] = pw[j];
#pragma unroll
        for (int j = 0; j < 8; j++)  x_s[tk * 33 + tg + 4 * j] = px[j];
        __syncthreads();
        if (kc + 32 < kc0 + 128) {
#pragma unroll
            for (int j = 0; j < 16; j++)
                pw[j] = ldg_el(W_ih + (o0 + tg + 4 * j) * XDIM + kc + 32 + tk, pol);
#pragma unroll
            for (int j = 0; j < 8; j++) {
                int b = tg + 4 * j, kg = kc + 32 + tk;
                px[j] = is_ctx ? g_ctx[b * E2D + kg]
                               : ldg_el(emb + (size_t)sh_id[b] * EMBD + (kg - E2D), pol);
            }
        }
#pragma unroll 4
        for (int k = 0; k < 32; k++) {
            const float* wr = &w_s[k * 65 + tx];
            float w0 = wr[0], w1 = wr[32];
            const float* hr = &x_s[k * 33 + ty * 8];
#pragma unroll
            for (int bj = 0; bj < 8; bj++) {
                float hb = hr[bj];
                acc[0][bj] = fmaf(w0, hb, acc[0][bj]);
                acc[1][bj] = fmaf(w1, hb, acc[1][bj]);
            }
        }
    }
#pragma unroll
    for (int vi = 0; vi < 2; vi++)
#pragma unroll
        for (int bj = 0; bj < 8; bj++)
            g_gip[(sp * 3 * DHID + o0 + tx + vi * 32) * B_SZ + ty * 8 + bj] = acc[vi][bj];
}

// ---------------- GRU elementwise: sum partials, gates, h_new ---------------
__global__ void __launch_bounds__(128) k_gruelem(const float* __restrict__ b_ih,
                                                 const float* __restrict__ b_hh) {
    int i = blockIdx.x * blockDim.x + threadIdx.x;
    if (i >= B_SZ * DHID) return;
    int b = i & 31, d = i >> 5;
    float gr = 0.f, gz = 0.f, gn = 0.f;
#pragma unroll
    for (int sp = 0; sp < NSPI; sp++) {
        int base = (sp * 3 * DHID + d) * B_SZ + b;
        gr += g_gip[base];
        gz += g_gip[base + DHID * B_SZ];
        gn += g_gip[base + 2 * DHID * B_SZ];
    }
    float hr = 0.f, hz = 0.f, hn = 0.f;
#pragma unroll
    for (int c = 0; c < NSPH; c++) {
        int base = (c * 3 * DHID + d) * B_SZ + b;
        hr += g_ghp[base];
        hz += g_ghp[base + DHID * B_SZ];
        hn += g_ghp[base + 2 * DHID * B_SZ];
    }
    float gir = gr + hr + b_ih[d] + b_hh[d];
    float giz = gz + hz + b_ih[DHID + d] + b_hh[DHID + d];
    float gin = gn + b_ih[2 * DHID + d];
    float ghn = hn + b_hh[2 * DHID + d];
    float r = 1.f / (1.f + expf(-gir));
    float z = 1.f / (1.f + expf(-giz));
    float n = tanhf(fmaf(r, ghn, gin));
    float ho = g_h[b * DHID + d];
    g_h[b * DHID + d] = fmaf(z, ho - n, n);
    if (i < B_SZ) g_amax[i] = 0ull;   // reset before this step's logits atomics
}

// ---------------- launch ----------------------------------------------------
extern "C" void kernel_launch(void* const* d_in, const int* in_sizes, int n_in,
                              void* d_out, int out_size) {
    const float* enc   = (const float*)d_in[0];
    const int*   sos_p = (const int*)  d_in[2];
    const float* emb   = (const float*)d_in[3];
    const float* W1    = (const float*)d_in[4];
    const float* b1    = (const float*)d_in[5];
    const float* W2    = (const float*)d_in[6];
    const float* b2    = (const float*)d_in[7];
    const float* W_ih  = (const float*)d_in[8];
    const float* b_ih  = (const float*)d_in[9];
    const float* W_hh  = (const float*)d_in[10];
    const float* b_hh  = (const float*)d_in[11];
    const float* Wo    = (const float*)d_in[12];
    const float* bo    = (const float*)d_in[13];
    float* out = (float*)d_out;

    int T = out_size / (B_SZ * VOCAB);
    const int smem_bytes = LOG_SMEM_FLOATS * 4;   // 82944

    cudaFuncSetAttribute(k_estep, cudaFuncAttributeMaxDynamicSharedMemorySize,
                         smem_bytes);

    k_init<<<64, 256>>>(sos_p);
    k_encproj<<<S_LEN * B_SZ / 8, 256>>>(enc, W1, b1);
    // prologue: attn(0) + gh(0), no logits
    k_estep<<<NBLK, 256, smem_bytes>>>(enc, W1, W2, b2, W_hh, Wo, bo, nullptr);

    for (int t = 0; t < T; t++) {
        k_gigemm<<<240, 128>>>(W_ih, emb);
        k_gruelem<<<128, 128>>>(b_ih, b_hh);
        // logits(t) + attn(t+1) + gh(t+1)  (the t=T-1 extras are harmless)
        k_estep<<<NBLK, 256, smem_bytes>>>(enc, W1, W2, b2, W_hh, Wo, bo,
                                           out + (size_t)t * B_SZ * VOCAB);
    }
}

// round 13
// speedup vs baseline: 1.1691x; 1.1691x over previous
#include <cuda_runtime.h>
#include <cstdint>

#define S_LEN  128
#define B_SZ   32
#define E2D    1024
#define DHID   512
#define AHID   32
#define EMBD   256
#define VOCAB  32000
#define CATD   1536   // DH + E2  (W1 row length)
#define XDIM   1280   // E2 + EMB (W_ih row length)
#define NSPI   10     // K-splits for gi (1280/128)
#define NSPH   4      // K-splits for gh (512/128)

// ---------------- device scratch (no allocation allowed) --------------------
__device__ __align__(16) float g_enc_proj[S_LEN * B_SZ * AHID]; // W1_enc@enc + b1
__device__ __align__(16) float g_h[B_SZ * DHID];                // hidden state
__device__ __align__(16) float g_ctx[B_SZ * E2D];               // attention context
__device__ __align__(16) float g_gip[NSPI * 3 * DHID * B_SZ];   // gi partials [sp][o][b]
__device__ __align__(16) float g_ghp[NSPH * 3 * DHID * B_SZ];   // gh partials [c][o][b]
__device__ unsigned long long g_amax[B_SZ];

// ---------------- helpers ---------------------------------------------------
__device__ __forceinline__ unsigned int fkey(float v) {
    unsigned int u = __float_as_uint(v);
    return (u & 0x80000000u) ? ~u : (u | 0x80000000u);
}
// larger value wins; on equal value LOWER index wins (jnp.argmax semantics)
__device__ __forceinline__ unsigned long long packkey(float v, int idx) {
    return ((unsigned long long)fkey(v) << 32) |
           (unsigned long long)(0x7FFFFFFFu - (unsigned int)idx);
}
__device__ __forceinline__ unsigned long long fdup(float x) {
    unsigned long long r;
    asm("mov.b64 %0, {%1, %1};" : "=l"(r) : "f"(x));
    return r;
}
__device__ __forceinline__ void ffma2(unsigned long long& d, unsigned long long a,
                                      unsigned long long b) {
    asm("fma.rn.f32x2 %0, %1, %2, %0;" : "+l"(d) : "l"(a), "l"(b));
}
__device__ __forceinline__ void funpk(float& lo, float& hi, unsigned long long v) {
    asm("mov.b64 {%0, %1}, %2;" : "=f"(lo), "=f"(hi) : "l"(v));
}
// evict_last policy — used ONLY for W_ih / W_hh (9.5 MB total)
__device__ __forceinline__ unsigned long long mk_policy_el() {
    unsigned long long pol;
    asm("createpolicy.fractional.L2::evict_last.b64 %0, 1.0;" : "=l"(pol));
    return pol;
}
__device__ __forceinline__ float ldg_el(const float* p, unsigned long long pol) {
    float v;
    asm("ld.global.nc.L2::cache_hint.f32 %0, [%1], %2;"
        : "=f"(v) : "l"(p), "l"(pol));
    return v;
}

// ---------------- init: h=0, amax encodes sos token -------------------------
__global__ void k_init(const int* __restrict__ sos_p) {
    int i = blockIdx.x * blockDim.x + threadIdx.x;
    if (i < B_SZ * DHID) g_h[i] = 0.0f;
    if (i < B_SZ) {
        int sos = *sos_p;
        g_amax[i] = (unsigned long long)(0x7FFFFFFFu - (unsigned int)sos);
    }
}

// ---------------- one-time: enc_proj[sb][a] = W1[a,512:]@enc[sb] + b1[a] ----
__global__ void k_encproj(const float* __restrict__ enc,
                          const float* __restrict__ W1,
                          const float* __restrict__ b1) {
    __shared__ float enc_sh[8 * E2D];
    int tid = threadIdx.x;
    int sb0 = blockIdx.x * 8;
    for (int i = tid; i < 8 * E2D; i += 256)
        enc_sh[i] = enc[sb0 * E2D + i];
    __syncthreads();
    int a = tid & 31;
    int r = tid >> 5;
    const float* w = W1 + a * CATD + DHID;
    const float* e = enc_sh + r * E2D;
    float a0 = 0.f, a1 = 0.f, a2 = 0.f, a3 = 0.f;
#pragma unroll 8
    for (int k = 0; k < E2D; k += 4) {
        a0 = fmaf(w[k],     e[k],     a0);
        a1 = fmaf(w[k + 1], e[k + 1], a1);
        a2 = fmaf(w[k + 2], e[k + 2], a2);
        a3 = fmaf(w[k + 3], e[k + 3], a3);
    }
    g_enc_proj[(sb0 + r) * AHID + a] = a0 + a1 + a2 + a3 + b1[a];
}

// =============================================================================
// k_estep: one launch doing three independent jobs (all depend only on g_h):
//   blocks [0,250)   : logits GEMM + fused argmax (f32x2 over b-pairs)
//   blocks [250,298) : gh partial GEMM for NEXT step   (W_hh @ h -> g_ghp)
//   blocks [298,330) : attention + context for NEXT step (-> g_ctx)
// =============================================================================
__global__ void __launch_bounds__(128) k_estep(
    const float* __restrict__ enc,
    const float* __restrict__ W1,
    const float* __restrict__ W2,
    const float* __restrict__ b2,
    const float* __restrict__ W_hh,
    const float* __restrict__ Wo,
    const float* __restrict__ bo,
    float* __restrict__ out_t) {
    __shared__ __align__(16) float sm[4128 + 1088];
    __shared__ unsigned long long bmax[B_SZ];
    int tid = threadIdx.x;
    int bk = blockIdx.x;

    if (bk < 250) {
        // ---- logits (f32x2 over b-pairs) + fused argmax --------------------
        if (out_t == nullptr) return;
        int v0 = bk * 128;
        float* wo_s = sm;              // [k][v] stride 129
        float* h_s  = sm + 4128;       // [k][b] stride 34 (8B-aligned pairs)
        int tk = tid & 31, tg = tid >> 5;
        int tx = tid & 31, ty = tid >> 5;
        if (tid < B_SZ) bmax[tid] = 0ull;

        unsigned long long acc[4][4];  // [v][b-pair]
#pragma unroll
        for (int i = 0; i < 4; i++)
#pragma unroll
            for (int j = 0; j < 4; j++) acc[i][j] = 0ull;

        float pw[32], ph[8];
        // prefetch chunk kc=0: thread covers k=tk fixed, v=tg+4j / b=tg+4j
#pragma unroll
        for (int j = 0; j < 32; j++)
            pw[j] = Wo[(size_t)(v0 + tg + 4 * j) * DHID + tk];
#pragma unroll
        for (int j = 0; j < 8; j++)
            ph[j] = g_h[(tg + 4 * j) * DHID + tk];

        for (int kc = 0; kc < DHID; kc += 32) {
            __syncthreads();
#pragma unroll
            for (int j = 0; j < 32; j++) wo_s[tk * 129 + tg + 4 * j] = pw[j];
#pragma unroll
            for (int j = 0; j < 8; j++)  h_s[tk * 34 + tg + 4 * j] = ph[j];
            __syncthreads();
            if (kc + 32 < DHID) {
#pragma unroll
                for (int j = 0; j < 32; j++)
                    pw[j] = Wo[(size_t)(v0 + tg + 4 * j) * DHID + kc + 32 + tk];
#pragma unroll
                for (int j = 0; j < 8; j++)
                    ph[j] = g_h[(tg + 4 * j) * DHID + kc + 32 + tk];
            }
#pragma unroll 2
            for (int k = 0; k < 32; k++) {
                const float* wr = &wo_s[k * 129 + tx];
                unsigned long long W0 = fdup(wr[0]);
                unsigned long long W1d = fdup(wr[32]);
                unsigned long long W2d = fdup(wr[64]);
                unsigned long long W3 = fdup(wr[96]);
                const unsigned long long* hp =
                    reinterpret_cast<const unsigned long long*>(h_s + k * 34 + ty * 8);
                unsigned long long H0 = hp[0], H1 = hp[1], H2 = hp[2], H3 = hp[3];
                ffma2(acc[0][0], W0, H0); ffma2(acc[0][1], W0, H1);
                ffma2(acc[0][2], W0, H2); ffma2(acc[0][3], W0, H3);
                ffma2(acc[1][0], W1d, H0); ffma2(acc[1][1], W1d, H1);
                ffma2(acc[1][2], W1d, H2); ffma2(acc[1][3], W1d, H3);
                ffma2(acc[2][0], W2d, H0); ffma2(acc[2][1], W2d, H1);
                ffma2(acc[2][2], W2d, H2); ffma2(acc[2][3], W2d, H3);
                ffma2(acc[3][0], W3, H0); ffma2(acc[3][1], W3, H1);
                ffma2(acc[3][2], W3, H2); ffma2(acc[3][3], W3, H3);
            }
        }

        int vb = v0 + tx;
        float bb0 = bo[vb], bb1 = bo[vb + 32], bb2 = bo[vb + 64], bb3 = bo[vb + 96];
#pragma unroll
        for (int p = 0; p < 4; p++) {
            int b0 = ty * 8 + 2 * p, b1 = b0 + 1;
            float x00, x01, x10, x11, x20, x21, x30, x31;
            funpk(x00, x01, acc[0][p]); funpk(x10, x11, acc[1][p]);
            funpk(x20, x21, acc[2][p]); funpk(x30, x31, acc[3][p]);
            x00 += bb0; x10 += bb1; x20 += bb2; x30 += bb3;
            x01 += bb0; x11 += bb1; x21 += bb2; x31 += bb3;
            float* o0 = out_t + (size_t)b0 * VOCAB + vb;
            float* o1 = out_t + (size_t)b1 * VOCAB + vb;
            // evict-first stores: keep L2 clean for weights
            __stcs(o0,      x00); __stcs(o0 + 32, x10);
            __stcs(o0 + 64, x20); __stcs(o0 + 96, x30);
            __stcs(o1,      x01); __stcs(o1 + 32, x11);
            __stcs(o1 + 64, x21); __stcs(o1 + 96, x31);
            float be0 = x00; int bi0 = vb;
            if (x10 > be0) { be0 = x10; bi0 = vb + 32; }
            if (x20 > be0) { be0 = x20; bi0 = vb + 64; }
            if (x30 > be0) { be0 = x30; bi0 = vb + 96; }
            float be1 = x01; int bi1 = vb;
            if (x11 > be1) { be1 = x11; bi1 = vb + 32; }
            if (x21 > be1) { be1 = x21; bi1 = vb + 64; }
            if (x31 > be1) { be1 = x31; bi1 = vb + 96; }
            atomicMax(&bmax[b0], packkey(be0, bi0));
            atomicMax(&bmax[b1], packkey(be1, bi1));
        }
        __syncthreads();
        if (tid < B_SZ) atomicMax(&g_amax[tid], bmax[tid]);
        return;
    }

    if (bk < 298) {
        // ---- gh partial: tile 128o x 32b, K range [c*128, c*128+128) -------
        unsigned long long pol = mk_policy_el();
        int r = bk - 250;
        int c = r & 3, ot = r >> 2;
        int o0 = ot * 128, kc0 = c * 128;
        float* w_s = sm;              // [k][o] stride 129
        float* x_s = sm + 4128;       // [k][b] stride 33
        int tk = tid & 31, tg = tid >> 5;
        int tx = tid & 31, ty = tid >> 5;
        float acc[4][8] = {};
        float pw[32], ph[8];
#pragma unroll
        for (int j = 0; j < 32; j++)
            pw[j] = ldg_el(W_hh + (o0 + tg + 4 * j) * DHID + kc0 + tk, pol);
#pragma unroll
        for (int j = 0; j < 8; j++)
            ph[j] = g_h[(tg + 4 * j) * DHID + kc0 + tk];
        for (int kc = kc0; kc < kc0 + 128; kc += 32) {
            __syncthreads();
#pragma unroll
            for (int j = 0; j < 32; j++) w_s[tk * 129 + tg + 4 * j] = pw[j];
#pragma unroll
            for (int j = 0; j < 8; j++)  x_s[tk * 33 + tg + 4 * j] = ph[j];
            __syncthreads();
            if (kc + 32 < kc0 + 128) {
#pragma unroll
                for (int j = 0; j < 32; j++)
                    pw[j] = ldg_el(W_hh + (o0 + tg + 4 * j) * DHID + kc + 32 + tk, pol);
#pragma unroll
                for (int j = 0; j < 8; j++)
                    ph[j] = g_h[(tg + 4 * j) * DHID + kc + 32 + tk];
            }
#pragma unroll 4
            for (int k = 0; k < 32; k++) {
                const float* wr = &w_s[k * 129 + tx];
                float w0 = wr[0], w1 = wr[32], w2 = wr[64], w3 = wr[96];
                const float* hr = &x_s[k * 33 + ty * 8];
#pragma unroll
                for (int bj = 0; bj < 8; bj++) {
                    float hb = hr[bj];
                    acc[0][bj] = fmaf(w0, hb, acc[0][bj]);
                    acc[1][bj] = fmaf(w1, hb, acc[1][bj]);
                    acc[2][bj] = fmaf(w2, hb, acc[2][bj]);
                    acc[3][bj] = fmaf(w3, hb, acc[3][bj]);
                }
            }
        }
#pragma unroll
        for (int vi = 0; vi < 4; vi++)
#pragma unroll
            for (int bj = 0; bj < 8; bj++)
                g_ghp[(c * 3 * DHID + o0 + tx + vi * 32) * B_SZ + ty * 8 + bj] = acc[vi][bj];
        return;
    }

    // ---- attention for next step, one block per batch ----------------------
    {
        int b = bk - 298;
        float* h_sh  = sm;         // 512
        float* part  = sm + 512;   // 4*32
        float* hproj = sm + 640;   // 32
        float* sc    = sm + 672;   // 128
        float* red   = sm + 800;   // 2
        for (int i = tid; i < DHID; i += 128) h_sh[i] = g_h[b * DHID + i];
        __syncthreads();
        {   // hproj[a] = W1[a,0:512] @ h : 4 segments of 128
            int a = tid & 31, seg = tid >> 5;
            const float* w  = W1 + a * CATD + seg * 128;
            const float* hh = h_sh + seg * 128;
            float acc = 0.f;
#pragma unroll 8
            for (int k = 0; k < 128; k++) acc = fmaf(w[k], hh[k], acc);
            part[seg * 32 + a] = acc;
        }
        __syncthreads();
        if (tid < AHID)
            hproj[tid] = part[tid] + part[32 + tid] + part[64 + tid] + part[96 + tid];
        __syncthreads();
        {   // scores over S (one thread per s)
            int s = tid;
            const float* ep = g_enc_proj + (s * B_SZ + b) * AHID;
            float sv = b2[0];
#pragma unroll
            for (int a = 0; a < AHID; a++) {
                float t = ep[a] + hproj[a];
                sv = fmaf(W2[a], fmaxf(t, 0.f), sv);
            }
            sc[s] = sv;
        }
        __syncthreads();
        if (tid < 32) {
            float m = fmaxf(fmaxf(sc[tid], sc[tid + 32]), fmaxf(sc[tid + 64], sc[tid + 96]));
#pragma unroll
            for (int off = 16; off > 0; off >>= 1)
                m = fmaxf(m, __shfl_xor_sync(0xffffffffu, m, off));
            if (tid == 0) red[0] = m;
        }
        __syncthreads();
        sc[tid] = expf(sc[tid] - red[0]);
        __syncthreads();
        if (tid < 32) {
            float s4 = sc[tid] + sc[tid + 32] + sc[tid + 64] + sc[tid + 96];
#pragma unroll
            for (int off = 16; off > 0; off >>= 1)
                s4 += __shfl_xor_sync(0xffffffffu, s4, off);
            if (tid == 0) red[1] = 1.0f / s4;
        }
        __syncthreads();
        sc[tid] *= red[1];
        __syncthreads();
        {   // context: each thread 8 consecutive e
            float acc[8] = {};
            const float4* e4 = reinterpret_cast<const float4*>(enc);
#pragma unroll 4
            for (int s = 0; s < S_LEN; s++) {
                float a = sc[s];
                int base4 = ((s * B_SZ + b) * E2D + tid * 8) >> 2;
                float4 v0 = e4[base4], v1 = e4[base4 + 1];
                acc[0] = fmaf(a, v0.x, acc[0]); acc[1] = fmaf(a, v0.y, acc[1]);
                acc[2] = fmaf(a, v0.z, acc[2]); acc[3] = fmaf(a, v0.w, acc[3]);
                acc[4] = fmaf(a, v1.x, acc[4]); acc[5] = fmaf(a, v1.y, acc[5]);
                acc[6] = fmaf(a, v1.z, acc[6]); acc[7] = fmaf(a, v1.w, acc[7]);
            }
            float* dst = g_ctx + b * E2D + tid * 8;
#pragma unroll
            for (int j = 0; j < 8; j++) dst[j] = acc[j];
        }
    }
}

// ---------------- gi partial GEMM (x = [ctx | emb[argmax]]) -----------------
// grid 240 blocks (24 o-tiles of 64 x 10 K-splits), 128 threads
__global__ void __launch_bounds__(128) k_gigemm(const float* __restrict__ W_ih,
                                                const float* __restrict__ emb) {
    __shared__ __align__(16) float w_s[32 * 65];
    __shared__ float x_s[32 * 33];
    __shared__ int sh_id[B_SZ];
    int tid = threadIdx.x;
    unsigned long long pol = mk_policy_el();
    int ot = blockIdx.x % 24, sp = blockIdx.x / 24;
    int o0 = ot * 64, kc0 = sp * 128;
    int tk = tid & 31, tg = tid >> 5;
    if (tid < B_SZ) {
        unsigned long long p = g_amax[tid];
        sh_id[tid] = (int)(0x7FFFFFFFu - (unsigned int)(p & 0x7FFFFFFFull));
    }
    __syncthreads();
    int tx = tid & 31, ty = tid >> 5;
    bool is_ctx = (kc0 < E2D);
    float acc[2][8] = {};
    float pw[16], px[8];
#pragma unroll
    for (int j = 0; j < 16; j++)
        pw[j] = ldg_el(W_ih + (o0 + tg + 4 * j) * XDIM + kc0 + tk, pol);
#pragma unroll
    for (int j = 0; j < 8; j++) {
        int b = tg + 4 * j, kg = kc0 + tk;
        px[j] = is_ctx ? g_ctx[b * E2D + kg]
                       : emb[(size_t)sh_id[b] * EMBD + (kg - E2D)];
    }
    for (int kc = kc0; kc < kc0 + 128; kc += 32) {
        __syncthreads();
#pragma unroll
        for (int j = 0; j < 16; j++) w_s[tk * 65 + tg + 4 * j] = pw[j];
#pragma unroll
        for (int j = 0; j < 8; j++)  x_s[tk * 33 + tg + 4 * j] = px[j];
        __syncthreads();
        if (kc + 32 < kc0 + 128) {
#pragma unroll
            for (int j = 0; j < 16; j++)
                pw[j] = ldg_el(W_ih + (o0 + tg + 4 * j) * XDIM + kc + 32 + tk, pol);
#pragma unroll
            for (int j = 0; j < 8; j++) {
                int b = tg + 4 * j, kg = kc + 32 + tk;
                px[j] = is_ctx ? g_ctx[b * E2D + kg]
                               : emb[(size_t)sh_id[b] * EMBD + (kg - E2D)];
            }
        }
#pragma unroll 4
        for (int k = 0; k < 32; k++) {
            const float* wr = &w_s[k * 65 + tx];
            float w0 = wr[0], w1 = wr[32];
            const float* hr = &x_s[k * 33 + ty * 8];
#pragma unroll
            for (int bj = 0; bj < 8; bj++) {
                float hb = hr[bj];
                acc[0][bj] = fmaf(w0, hb, acc[0][bj]);
                acc[1][bj] = fmaf(w1, hb, acc[1][bj]);
            }
        }
    }
#pragma unroll
    for (int vi = 0; vi < 2; vi++)
#pragma unroll
        for (int bj = 0; bj < 8; bj++)
            g_gip[(sp * 3 * DHID + o0 + tx + vi * 32) * B_SZ + ty * 8 + bj] = acc[vi][bj];
}

// ---------------- GRU elementwise: sum partials, gates, h_new ---------------
__global__ void __launch_bounds__(128) k_gruelem(const float* __restrict__ b_ih,
                                                 const float* __restrict__ b_hh) {
    int i = blockIdx.x * blockDim.x + threadIdx.x;
    if (i >= B_SZ * DHID) return;
    int b = i & 31, d = i >> 5;
    float gr = 0.f, gz = 0.f, gn = 0.f;
#pragma unroll
    for (int sp = 0; sp < NSPI; sp++) {
        int base = (sp * 3 * DHID + d) * B_SZ + b;
        gr += g_gip[base];
        gz += g_gip[base + DHID * B_SZ];
        gn += g_gip[base + 2 * DHID * B_SZ];
    }
    float hr = 0.f, hz = 0.f, hn = 0.f;
#pragma unroll
    for (int c = 0; c < NSPH; c++) {
        int base = (c * 3 * DHID + d) * B_SZ + b;
        hr += g_ghp[base];
        hz += g_ghp[base + DHID * B_SZ];
        hn += g_ghp[base + 2 * DHID * B_SZ];
    }
    float gir = gr + hr + b_ih[d] + b_hh[d];
    float giz = gz + hz + b_ih[DHID + d] + b_hh[DHID + d];
    float gin = gn + b_ih[2 * DHID + d];
    float ghn = hn + b_hh[2 * DHID + d];
    float r = 1.f / (1.f + expf(-gir));
    float z = 1.f / (1.f + expf(-giz));
    float n = tanhf(fmaf(r, ghn, gin));
    float ho = g_h[b * DHID + d];
    g_h[b * DHID + d] = fmaf(z, ho - n, n);
    if (i < B_SZ) g_amax[i] = 0ull;   // reset before this step's logits atomics
}

// ---------------- launch ----------------------------------------------------
extern "C" void kernel_launch(void* const* d_in, const int* in_sizes, int n_in,
                              void* d_out, int out_size) {
    const float* enc   = (const float*)d_in[0];
    const int*   sos_p = (const int*)  d_in[2];
    const float* emb   = (const float*)d_in[3];
    const float* W1    = (const float*)d_in[4];
    const float* b1    = (const float*)d_in[5];
    const float* W2    = (const float*)d_in[6];
    const float* b2    = (const float*)d_in[7];
    const float* W_ih  = (const float*)d_in[8];
    const float* b_ih  = (const float*)d_in[9];
    const float* W_hh  = (const float*)d_in[10];
    const float* b_hh  = (const float*)d_in[11];
    const float* Wo    = (const float*)d_in[12];
    const float* bo    = (const float*)d_in[13];
    float* out = (float*)d_out;

    int T = out_size / (B_SZ * VOCAB);

    k_init<<<64, 256>>>(sos_p);
    k_encproj<<<S_LEN * B_SZ / 8, 256>>>(enc, W1, b1);
    // prologue: attn(0) + gh(0), no logits
    k_estep<<<330, 128>>>(enc, W1, W2, b2, W_hh, Wo, bo, nullptr);

    for (int t = 0; t < T; t++) {
        k_gigemm<<<240, 128>>>(W_ih, emb);
        k_gruelem<<<128, 128>>>(b_ih, b_hh);
        // logits(t) + attn(t+1) + gh(t+1)  (the t=T-1 extras are harmless)
        k_estep<<<330, 128>>>(enc, W1, W2, b2, W_hh, Wo, bo,
                              out + (size_t)t * B_SZ * VOCAB);
    }
}

// round 14
// speedup vs baseline: 1.2119x; 1.0366x over previous
#include <cuda_runtime.h>
#include <cstdint>

#define S_LEN  128
#define B_SZ   32
#define E2D    1024
#define DHID   512
#define AHID   32
#define EMBD   256
#define VOCAB  32000
#define CATD   1536   // DH + E2  (W1 row length)
#define XDIM   1280   // E2 + EMB (W_ih row length)
#define NSPI   10     // K-splits for gi (1280/128)
#define NSPH   4      // K-splits for gh (512/128)

// ---------------- device scratch (no allocation allowed) --------------------
__device__ __align__(16) float g_enc_proj[S_LEN * B_SZ * AHID]; // W1_enc@enc + b1
__device__ __align__(16) float g_h[B_SZ * DHID];                // hidden state
__device__ __align__(16) float g_ctx[B_SZ * E2D];               // attention context
__device__ __align__(16) float g_gip[NSPI * 3 * DHID * B_SZ];   // gi partials [sp][o][b]
__device__ __align__(16) float g_ghp[NSPH * 3 * DHID * B_SZ];   // gh partials [c][o][b]
__device__ unsigned long long g_amax[B_SZ];

// ---------------- helpers ---------------------------------------------------
__device__ __forceinline__ unsigned int fkey(float v) {
    unsigned int u = __float_as_uint(v);
    return (u & 0x80000000u) ? ~u : (u | 0x80000000u);
}
// larger value wins; on equal value LOWER index wins (jnp.argmax semantics)
__device__ __forceinline__ unsigned long long packkey(float v, int idx) {
    return ((unsigned long long)fkey(v) << 32) |
           (unsigned long long)(0x7FFFFFFFu - (unsigned int)idx);
}
__device__ __forceinline__ unsigned long long fdup(float x) {
    unsigned long long r;
    asm("mov.b64 %0, {%1, %1};" : "=l"(r) : "f"(x));
    return r;
}
__device__ __forceinline__ void ffma2(unsigned long long& d, unsigned long long a,
                                      unsigned long long b) {
    asm("fma.rn.f32x2 %0, %1, %2, %0;" : "+l"(d) : "l"(a), "l"(b));
}
__device__ __forceinline__ void funpk(float& lo, float& hi, unsigned long long v) {
    asm("mov.b64 {%0, %1}, %2;" : "=f"(lo), "=f"(hi) : "l"(v));
}
// evict_last policy — protect the per-step-reused weights (Wo, W_ih, W_hh)
__device__ __forceinline__ unsigned long long mk_policy_el() {
    unsigned long long pol;
    asm("createpolicy.fractional.L2::evict_last.b64 %0, 1.0;" : "=l"(pol));
    return pol;
}
__device__ __forceinline__ float ldg_el(const float* p, unsigned long long pol) {
    float v;
    asm("ld.global.nc.L2::cache_hint.f32 %0, [%1], %2;"
        : "=f"(v) : "l"(p), "l"(pol));
    return v;
}

// ---------------- init: h=0, amax encodes sos token -------------------------
__global__ void k_init(const int* __restrict__ sos_p) {
    int i = blockIdx.x * blockDim.x + threadIdx.x;
    if (i < B_SZ * DHID) g_h[i] = 0.0f;
    if (i < B_SZ) {
        int sos = *sos_p;
        g_amax[i] = (unsigned long long)(0x7FFFFFFFu - (unsigned int)sos);
    }
}

// ---------------- one-time: enc_proj[sb][a] = W1[a,512:]@enc[sb] + b1[a] ----
__global__ void k_encproj(const float* __restrict__ enc,
                          const float* __restrict__ W1,
                          const float* __restrict__ b1) {
    __shared__ float enc_sh[8 * E2D];
    int tid = threadIdx.x;
    int sb0 = blockIdx.x * 8;
    for (int i = tid; i < 8 * E2D; i += 256)
        enc_sh[i] = enc[sb0 * E2D + i];
    __syncthreads();
    int a = tid & 31;
    int r = tid >> 5;
    const float* w = W1 + a * CATD + DHID;
    const float* e = enc_sh + r * E2D;
    float a0 = 0.f, a1 = 0.f, a2 = 0.f, a3 = 0.f;
#pragma unroll 8
    for (int k = 0; k < E2D; k += 4) {
        a0 = fmaf(w[k],     e[k],     a0);
        a1 = fmaf(w[k + 1], e[k + 1], a1);
        a2 = fmaf(w[k + 2], e[k + 2], a2);
        a3 = fmaf(w[k + 3], e[k + 3], a3);
    }
    g_enc_proj[(sb0 + r) * AHID + a] = a0 + a1 + a2 + a3 + b1[a];
}

// =============================================================================
// k_estep: one launch doing three independent jobs (all depend only on g_h):
//   blocks [0,250)   : logits GEMM + fused argmax (f32x2 over b-pairs)
//   blocks [250,298) : gh partial GEMM for NEXT step   (W_hh @ h -> g_ghp)
//   blocks [298,330) : attention + context for NEXT step (-> g_ctx)
// =============================================================================
__global__ void __launch_bounds__(128) k_estep(
    const float* __restrict__ enc,
    const float* __restrict__ W1,
    const float* __restrict__ W2,
    const float* __restrict__ b2,
    const float* __restrict__ W_hh,
    const float* __restrict__ Wo,
    const float* __restrict__ bo,
    float* __restrict__ out_t) {
    __shared__ __align__(16) float sm[4128 + 1088];
    __shared__ unsigned long long bmax[B_SZ];
    int tid = threadIdx.x;
    int bk = blockIdx.x;

    if (bk < 250) {
        // ---- logits (f32x2 over b-pairs) + fused argmax --------------------
        if (out_t == nullptr) return;
        unsigned long long pol = mk_policy_el();
        int v0 = bk * 128;
        float* wo_s = sm;              // [k][v] stride 129
        float* h_s  = sm + 4128;       // [k][b] stride 34 (8B-aligned pairs)
        int tk = tid & 31, tg = tid >> 5;
        int tx = tid & 31, ty = tid >> 5;
        if (tid < B_SZ) bmax[tid] = 0ull;

        unsigned long long acc[4][4];  // [v][b-pair]
#pragma unroll
        for (int i = 0; i < 4; i++)
#pragma unroll
            for (int j = 0; j < 4; j++) acc[i][j] = 0ull;

        float pw[32], ph[8];
        // prefetch chunk kc=0: thread covers k=tk fixed, v=tg+4j / b=tg+4j
        // Wo loads carry evict_last so the 64 MB Wo set survives in L2
        // across (and within) steps; output stores below are evict-first.
#pragma unroll
        for (int j = 0; j < 32; j++)
            pw[j] = ldg_el(Wo + (size_t)(v0 + tg + 4 * j) * DHID + tk, pol);
#pragma unroll
        for (int j = 0; j < 8; j++)
            ph[j] = g_h[(tg + 4 * j) * DHID + tk];

        for (int kc = 0; kc < DHID; kc += 32) {
            __syncthreads();
#pragma unroll
            for (int j = 0; j < 32; j++) wo_s[tk * 129 + tg + 4 * j] = pw[j];
#pragma unroll
            for (int j = 0; j < 8; j++)  h_s[tk * 34 + tg + 4 * j] = ph[j];
            __syncthreads();
            if (kc + 32 < DHID) {
#pragma unroll
                for (int j = 0; j < 32; j++)
                    pw[j] = ldg_el(Wo + (size_t)(v0 + tg + 4 * j) * DHID
                                      + kc + 32 + tk, pol);
#pragma unroll
                for (int j = 0; j < 8; j++)
                    ph[j] = g_h[(tg + 4 * j) * DHID + kc + 32 + tk];
            }
#pragma unroll 2
            for (int k = 0; k < 32; k++) {
                const float* wr = &wo_s[k * 129 + tx];
                unsigned long long W0 = fdup(wr[0]);
                unsigned long long W1d = fdup(wr[32]);
                unsigned long long W2d = fdup(wr[64]);
                unsigned long long W3 = fdup(wr[96]);
                const unsigned long long* hp =
                    reinterpret_cast<const unsigned long long*>(h_s + k * 34 + ty * 8);
                unsigned long long H0 = hp[0], H1 = hp[1], H2 = hp[2], H3 = hp[3];
                ffma2(acc[0][0], W0, H0); ffma2(acc[0][1], W0, H1);
                ffma2(acc[0][2], W0, H2); ffma2(acc[0][3], W0, H3);
                ffma2(acc[1][0], W1d, H0); ffma2(acc[1][1], W1d, H1);
                ffma2(acc[1][2], W1d, H2); ffma2(acc[1][3], W1d, H3);
                ffma2(acc[2][0], W2d, H0); ffma2(acc[2][1], W2d, H1);
                ffma2(acc[2][2], W2d, H2); ffma2(acc[2][3], W2d, H3);
                ffma2(acc[3][0], W3, H0); ffma2(acc[3][1], W3, H1);
                ffma2(acc[3][2], W3, H2); ffma2(acc[3][3], W3, H3);
            }
        }

        int vb = v0 + tx;
        float bb0 = bo[vb], bb1 = bo[vb + 32], bb2 = bo[vb + 64], bb3 = bo[vb + 96];
#pragma unroll
        for (int p = 0; p < 4; p++) {
            int b0 = ty * 8 + 2 * p, b1 = b0 + 1;
            float x00, x01, x10, x11, x20, x21, x30, x31;
            funpk(x00, x01, acc[0][p]); funpk(x10, x11, acc[1][p]);
            funpk(x20, x21, acc[2][p]); funpk(x30, x31, acc[3][p]);
            x00 += bb0; x10 += bb1; x20 += bb2; x30 += bb3;
            x01 += bb0; x11 += bb1; x21 += bb2; x31 += bb3;
            float* o0 = out_t + (size_t)b0 * VOCAB + vb;
            float* o1 = out_t + (size_t)b1 * VOCAB + vb;
            // evict-first stores: keep L2 for the protected weight set
            __stcs(o0,      x00); __stcs(o0 + 32, x10);
            __stcs(o0 + 64, x20); __stcs(o0 + 96, x30);
            __stcs(o1,      x01); __stcs(o1 + 32, x11);
            __stcs(o1 + 64, x21); __stcs(o1 + 96, x31);
            float be0 = x00; int bi0 = vb;
            if (x10 > be0) { be0 = x10; bi0 = vb + 32; }
            if (x20 > be0) { be0 = x20; bi0 = vb + 64; }
            if (x30 > be0) { be0 = x30; bi0 = vb + 96; }
            float be1 = x01; int bi1 = vb;
            if (x11 > be1) { be1 = x11; bi1 = vb + 32; }
            if (x21 > be1) { be1 = x21; bi1 = vb + 64; }
            if (x31 > be1) { be1 = x31; bi1 = vb + 96; }
            atomicMax(&bmax[b0], packkey(be0, bi0));
            atomicMax(&bmax[b1], packkey(be1, bi1));
        }
        __syncthreads();
        if (tid < B_SZ) atomicMax(&g_amax[tid], bmax[tid]);
        return;
    }

    if (bk < 298) {
        // ---- gh partial: tile 128o x 32b, K range [c*128, c*128+128) -------
        unsigned long long pol = mk_policy_el();
        int r = bk - 250;
        int c = r & 3, ot = r >> 2;
        int o0 = ot * 128, kc0 = c * 128;
        float* w_s = sm;              // [k][o] stride 129
        float* x_s = sm + 4128;       // [k][b] stride 33
        int tk = tid & 31, tg = tid >> 5;
        int tx = tid & 31, ty = tid >> 5;
        float acc[4][8] = {};
        float pw[32], ph[8];
#pragma unroll
        for (int j = 0; j < 32; j++)
            pw[j] = ldg_el(W_hh + (o0 + tg + 4 * j) * DHID + kc0 + tk, pol);
#pragma unroll
        for (int j = 0; j < 8; j++)
            ph[j] = g_h[(tg + 4 * j) * DHID + kc0 + tk];
        for (int kc = kc0; kc < kc0 + 128; kc += 32) {
            __syncthreads();
#pragma unroll
            for (int j = 0; j < 32; j++) w_s[tk * 129 + tg + 4 * j] = pw[j];
#pragma unroll
            for (int j = 0; j < 8; j++)  x_s[tk * 33 + tg + 4 * j] = ph[j];
            __syncthreads();
            if (kc + 32 < kc0 + 128) {
#pragma unroll
                for (int j = 0; j < 32; j++)
                    pw[j] = ldg_el(W_hh + (o0 + tg + 4 * j) * DHID + kc + 32 + tk, pol);
#pragma unroll
                for (int j = 0; j < 8; j++)
                    ph[j] = g_h[(tg + 4 * j) * DHID + kc + 32 + tk];
            }
#pragma unroll 4
            for (int k = 0; k < 32; k++) {
                const float* wr = &w_s[k * 129 + tx];
                float w0 = wr[0], w1 = wr[32], w2 = wr[64], w3 = wr[96];
                const float* hr = &x_s[k * 33 + ty * 8];
#pragma unroll
                for (int bj = 0; bj < 8; bj++) {
                    float hb = hr[bj];
                    acc[0][bj] = fmaf(w0, hb, acc[0][bj]);
                    acc[1][bj] = fmaf(w1, hb, acc[1][bj]);
                    acc[2][bj] = fmaf(w2, hb, acc[2][bj]);
                    acc[3][bj] = fmaf(w3, hb, acc[3][bj]);
                }
            }
        }
#pragma unroll
        for (int vi = 0; vi < 4; vi++)
#pragma unroll
            for (int bj = 0; bj < 8; bj++)
                g_ghp[(c * 3 * DHID + o0 + tx + vi * 32) * B_SZ + ty * 8 + bj] = acc[vi][bj];
        return;
    }

    // ---- attention for next step, one block per batch ----------------------
    {
        int b = bk - 298;
        float* h_sh  = sm;         // 512
        float* part  = sm + 512;   // 4*32
        float* hproj = sm + 640;   // 32
        float* sc    = sm + 672;   // 128
        float* red   = sm + 800;   // 2
        for (int i = tid; i < DHID; i += 128) h_sh[i] = g_h[b * DHID + i];
        __syncthreads();
        {   // hproj[a] = W1[a,0:512] @ h : 4 segments of 128
            int a = tid & 31, seg = tid >> 5;
            const float* w  = W1 + a * CATD + seg * 128;
            const float* hh = h_sh + seg * 128;
            float acc = 0.f;
#pragma unroll 8
            for (int k = 0; k < 128; k++) acc = fmaf(w[k], hh[k], acc);
            part[seg * 32 + a] = acc;
        }
        __syncthreads();
        if (tid < AHID)
            hproj[tid] = part[tid] + part[32 + tid] + part[64 + tid] + part[96 + tid];
        __syncthreads();
        {   // scores over S (one thread per s)
            int s = tid;
            const float* ep = g_enc_proj + (s * B_SZ + b) * AHID;
            float sv = b2[0];
#pragma unroll
            for (int a = 0; a < AHID; a++) {
                float t = ep[a] + hproj[a];
                sv = fmaf(W2[a], fmaxf(t, 0.f), sv);
            }
            sc[s] = sv;
        }
        __syncthreads();
        if (tid < 32) {
            float m = fmaxf(fmaxf(sc[tid], sc[tid + 32]), fmaxf(sc[tid + 64], sc[tid + 96]));
#pragma unroll
            for (int off = 16; off > 0; off >>= 1)
                m = fmaxf(m, __shfl_xor_sync(0xffffffffu, m, off));
            if (tid == 0) red[0] = m;
        }
        __syncthreads();
        sc[tid] = expf(sc[tid] - red[0]);
        __syncthreads();
        if (tid < 32) {
            float s4 = sc[tid] + sc[tid + 32] + sc[tid + 64] + sc[tid + 96];
#pragma unroll
            for (int off = 16; off > 0; off >>= 1)
                s4 += __shfl_xor_sync(0xffffffffu, s4, off);
            if (tid == 0) red[1] = 1.0f / s4;
        }
        __syncthreads();
        sc[tid] *= red[1];
        __syncthreads();
        {   // context: each thread 8 consecutive e
            float acc[8] = {};
            const float4* e4 = reinterpret_cast<const float4*>(enc);
#pragma unroll 4
            for (int s = 0; s < S_LEN; s++) {
                float a = sc[s];
                int base4 = ((s * B_SZ + b) * E2D + tid * 8) >> 2;
                float4 v0 = e4[base4], v1 = e4[base4 + 1];
                acc[0] = fmaf(a, v0.x, acc[0]); acc[1] = fmaf(a, v0.y, acc[1]);
                acc[2] = fmaf(a, v0.z, acc[2]); acc[3] = fmaf(a, v0.w, acc[3]);
                acc[4] = fmaf(a, v1.x, acc[4]); acc[5] = fmaf(a, v1.y, acc[5]);
                acc[6] = fmaf(a, v1.z, acc[6]); acc[7] = fmaf(a, v1.w, acc[7]);
            }
            float* dst = g_ctx + b * E2D + tid * 8;
#pragma unroll
            for (int j = 0; j < 8; j++) dst[j] = acc[j];
        }
    }
}

// ---------------- gi partial GEMM (x = [ctx | emb[argmax]]) -----------------
// grid 240 blocks (24 o-tiles of 64 x 10 K-splits), 128 threads
__global__ void __launch_bounds__(128) k_gigemm(const float* __restrict__ W_ih,
                                                const float* __restrict__ emb) {
    __shared__ __align__(16) float w_s[32 * 65];
    __shared__ float x_s[32 * 33];
    __shared__ int sh_id[B_SZ];
    int tid = threadIdx.x;
    unsigned long long pol = mk_policy_el();
    int ot = blockIdx.x % 24, sp = blockIdx.x / 24;
    int o0 = ot * 64, kc0 = sp * 128;
    int tk = tid & 31, tg = tid >> 5;
    if (tid < B_SZ) {
        unsigned long long p = g_amax[tid];
        sh_id[tid] = (int)(0x7FFFFFFFu - (unsigned int)(p & 0x7FFFFFFFull));
    }
    __syncthreads();
    int tx = tid & 31, ty = tid >> 5;
    bool is_ctx = (kc0 < E2D);
    float acc[2][8] = {};
    float pw[16], px[8];
#pragma unroll
    for (int j = 0; j < 16; j++)
        pw[j] = ldg_el(W_ih + (o0 + tg + 4 * j) * XDIM + kc0 + tk, pol);
#pragma unroll
    for (int j = 0; j < 8; j++) {
        int b = tg + 4 * j, kg = kc0 + tk;
        px[j] = is_ctx ? g_ctx[b * E2D + kg]
                       : emb[(size_t)sh_id[b] * EMBD + (kg - E2D)];
    }
    for (int kc = kc0; kc < kc0 + 128; kc += 32) {
        __syncthreads();
#pragma unroll
        for (int j = 0; j < 16; j++) w_s[tk * 65 + tg + 4 * j] = pw[j];
#pragma unroll
        for (int j = 0; j < 8; j++)  x_s[tk * 33 + tg + 4 * j] = px[j];
        __syncthreads();
        if (kc + 32 < kc0 + 128) {
#pragma unroll
            for (int j = 0; j < 16; j++)
                pw[j] = ldg_el(W_ih + (o0 + tg + 4 * j) * XDIM + kc + 32 + tk, pol);
#pragma unroll
            for (int j = 0; j < 8; j++) {
                int b = tg + 4 * j, kg = kc + 32 + tk;
                px[j] = is_ctx ? g_ctx[b * E2D + kg]
                               : emb[(size_t)sh_id[b] * EMBD + (kg - E2D)];
            }
        }
#pragma unroll 4
        for (int k = 0; k < 32; k++) {
            const float* wr = &w_s[k * 65 + tx];
            float w0 = wr[0], w1 = wr[32];
            const float* hr = &x_s[k * 33 + ty * 8];
#pragma unroll
            for (int bj = 0; bj < 8; bj++) {
                float hb = hr[bj];
                acc[0][bj] = fmaf(w0, hb, acc[0][bj]);
                acc[1][bj] = fmaf(w1, hb, acc[1][bj]);
            }
        }
    }
#pragma unroll
    for (int vi = 0; vi < 2; vi++)
#pragma unroll
        for (int bj = 0; bj < 8; bj++)
            g_gip[(sp * 3 * DHID + o0 + tx + vi * 32) * B_SZ + ty * 8 + bj] = acc[vi][bj];
}

// ---------------- GRU elementwise: sum partials, gates, h_new ---------------
__global__ void __launch_bounds__(128) k_gruelem(const float* __restrict__ b_ih,
                                                 const float* __restrict__ b_hh) {
    int i = blockIdx.x * blockDim.x + threadIdx.x;
    if (i >= B_SZ * DHID) return;
    int b = i & 31, d = i >> 5;
    float gr = 0.f, gz = 0.f, gn = 0.f;
#pragma unroll
    for (int sp = 0; sp < NSPI; sp++) {
        int base = (sp * 3 * DHID + d) * B_SZ + b;
        gr += g_gip[base];
        gz += g_gip[base + DHID * B_SZ];
        gn += g_gip[base + 2 * DHID * B_SZ];
    }
    float hr = 0.f, hz = 0.f, hn = 0.f;
#pragma unroll
    for (int c = 0; c < NSPH; c++) {
        int base = (c * 3 * DHID + d) * B_SZ + b;
        hr += g_ghp[base];
        hz += g_ghp[base + DHID * B_SZ];
        hn += g_ghp[base + 2 * DHID * B_SZ];
    }
    float gir = gr + hr + b_ih[d] + b_hh[d];
    float giz = gz + hz + b_ih[DHID + d] + b_hh[DHID + d];
    float gin = gn + b_ih[2 * DHID + d];
    float ghn = hn + b_hh[2 * DHID + d];
    float r = 1.f / (1.f + expf(-gir));
    float z = 1.f / (1.f + expf(-giz));
    float n = tanhf(fmaf(r, ghn, gin));
    float ho = g_h[b * DHID + d];
    g_h[b * DHID + d] = fmaf(z, ho - n, n);
    if (i < B_SZ) g_amax[i] = 0ull;   // reset before this step's logits atomics
}

// ---------------- launch ----------------------------------------------------
extern "C" void kernel_launch(void* const* d_in, const int* in_sizes, int n_in,
                              void* d_out, int out_size) {
    const float* enc   = (const float*)d_in[0];
    const int*   sos_p = (const int*)  d_in[2];
    const float* emb   = (const float*)d_in[3];
    const float* W1    = (const float*)d_in[4];
    const float* b1    = (const float*)d_in[5];
    const float* W2    = (const float*)d_in[6];
    const float* b2    = (const float*)d_in[7];
    const float* W_ih  = (const float*)d_in[8];
    const float* b_ih  = (const float*)d_in[9];
    const float* W_hh  = (const float*)d_in[10];
    const float* b_hh  = (const float*)d_in[11];
    const float* Wo    = (const float*)d_in[12];
    const float* bo    = (const float*)d_in[13];
    float* out = (float*)d_out;

    int T = out_size / (B_SZ * VOCAB);

    k_init<<<64, 256>>>(sos_p);
    k_encproj<<<S_LEN * B_SZ / 8, 256>>>(enc, W1, b1);
    // prologue: attn(0) + gh(0), no logits
    k_estep<<<330, 128>>>(enc, W1, W2, b2, W_hh, Wo, bo, nullptr);

    for (int t = 0; t < T; t++) {
        k_gigemm<<<240, 128>>>(W_ih, emb);
        k_gruelem<<<128, 128>>>(b_ih, b_hh);
        // logits(t) + attn(t+1) + gh(t+1)  (the t=T-1 extras are harmless)
        k_estep<<<330, 128>>>(enc, W1, W2, b2, W_hh, Wo, bo,
                              out + (size_t)t * B_SZ * VOCAB);
    }
}

// round 15
// speedup vs baseline: 1.2559x; 1.0363x over previous
#include <cuda_runtime.h>
#include <cstdint>

#define S_LEN  128
#define B_SZ   32
#define E2D    1024
#define DHID   512
#define AHID   32
#define EMBD   256
#define VOCAB  32000
#define CATD   1536   // DH + E2  (W1 row length)
#define XDIM   1280   // E2 + EMB (W_ih row length)
#define NSPI   10     // K-splits for gi (1280/128)
#define NSPH   4      // K-splits for gh (512/128)

#define LSTR   36     // logits smem row stride (floats), 144 B (16B-aligned)

// ---------------- device scratch (no allocation allowed) --------------------
__device__ __align__(16) float g_enc_proj[S_LEN * B_SZ * AHID]; // W1_enc@enc + b1
__device__ __align__(16) float g_h[B_SZ * DHID];                // hidden state
__device__ __align__(16) float g_ctx[B_SZ * E2D];               // attention context
__device__ __align__(16) float g_gip[NSPI * 3 * DHID * B_SZ];   // gi partials [sp][o][b]
__device__ __align__(16) float g_ghp[NSPH * 3 * DHID * B_SZ];   // gh partials [c][o][b]
__device__ unsigned long long g_amax[B_SZ];

// ---------------- helpers ---------------------------------------------------
__device__ __forceinline__ unsigned int fkey(float v) {
    unsigned int u = __float_as_uint(v);
    return (u & 0x80000000u) ? ~u : (u | 0x80000000u);
}
// larger value wins; on equal value LOWER index wins (jnp.argmax semantics)
__device__ __forceinline__ unsigned long long packkey(float v, int idx) {
    return ((unsigned long long)fkey(v) << 32) |
           (unsigned long long)(0x7FFFFFFFu - (unsigned int)idx);
}
__device__ __forceinline__ void ffma2(unsigned long long& d, unsigned long long a,
                                      unsigned long long b) {
    asm("fma.rn.f32x2 %0, %1, %2, %0;" : "+l"(d) : "l"(a), "l"(b));
}
__device__ __forceinline__ float fcollapse(unsigned long long v) {
    float lo, hi;
    asm("mov.b64 {%0, %1}, %2;" : "=f"(lo), "=f"(hi) : "l"(v));
    return lo + hi;
}
// evict_last policy — protect the per-step-reused weights (Wo, W_ih, W_hh)
__device__ __forceinline__ unsigned long long mk_policy_el() {
    unsigned long long pol;
    asm("createpolicy.fractional.L2::evict_last.b64 %0, 1.0;" : "=l"(pol));
    return pol;
}
__device__ __forceinline__ float ldg_el(const float* p, unsigned long long pol) {
    float v;
    asm("ld.global.nc.L2::cache_hint.f32 %0, [%1], %2;"
        : "=f"(v) : "l"(p), "l"(pol));
    return v;
}

// ---------------- init: h=0, amax encodes sos token -------------------------
__global__ void k_init(const int* __restrict__ sos_p) {
    int i = blockIdx.x * blockDim.x + threadIdx.x;
    if (i < B_SZ * DHID) g_h[i] = 0.0f;
    if (i < B_SZ) {
        int sos = *sos_p;
        g_amax[i] = (unsigned long long)(0x7FFFFFFFu - (unsigned int)sos);
    }
}

// ---------------- one-time: enc_proj[sb][a] = W1[a,512:]@enc[sb] + b1[a] ----
__global__ void k_encproj(const float* __restrict__ enc,
                          const float* __restrict__ W1,
                          const float* __restrict__ b1) {
    __shared__ float enc_sh[8 * E2D];
    int tid = threadIdx.x;
    int sb0 = blockIdx.x * 8;
    for (int i = tid; i < 8 * E2D; i += 256)
        enc_sh[i] = enc[sb0 * E2D + i];
    __syncthreads();
    int a = tid & 31;
    int r = tid >> 5;
    const float* w = W1 + a * CATD + DHID;
    const float* e = enc_sh + r * E2D;
    float a0 = 0.f, a1 = 0.f, a2 = 0.f, a3 = 0.f;
#pragma unroll 8
    for (int k = 0; k < E2D; k += 4) {
        a0 = fmaf(w[k],     e[k],     a0);
        a1 = fmaf(w[k + 1], e[k + 1], a1);
        a2 = fmaf(w[k + 2], e[k + 2], a2);
        a3 = fmaf(w[k + 3], e[k + 3], a3);
    }
    g_enc_proj[(sb0 + r) * AHID + a] = a0 + a1 + a2 + a3 + b1[a];
}

// =============================================================================
// k_estep: one launch doing three independent jobs (all depend only on g_h):
//   blocks [0,250)   : logits GEMM + fused argmax (f32x2 packed over k-pairs)
//   blocks [250,298) : gh partial GEMM for NEXT step   (W_hh @ h -> g_ghp)
//   blocks [298,330) : attention + context for NEXT step (-> g_ctx)
// =============================================================================
__global__ void __launch_bounds__(128) k_estep(
    const float* __restrict__ enc,
    const float* __restrict__ W1,
    const float* __restrict__ W2,
    const float* __restrict__ b2,
    const float* __restrict__ W_hh,
    const float* __restrict__ Wo,
    const float* __restrict__ bo,
    float* __restrict__ out_t) {
    __shared__ __align__(16) float sm[128 * LSTR + 32 * LSTR];  // 5760 floats
    __shared__ unsigned long long bmax[B_SZ];
    int tid = threadIdx.x;
    int bk = blockIdx.x;

    if (bk < 250) {
        // ---- logits: k-pair f32x2, [v][k]/[b][k] smem, no fdup -------------
        if (out_t == nullptr) return;
        unsigned long long pol = mk_policy_el();
        int v0 = bk * 128;
        float* wo_s = sm;                     // [v][k] stride 36, 128 rows
        float* h_s  = sm + 128 * LSTR;        // [b][k] stride 36, 32 rows
        int tk = tid & 31, tg = tid >> 5;
        int w  = tid >> 5, tx = tid & 31;
        int vg = w & 1;                        // v half (64)
        int bg = w >> 1;                       // b half (16)
        int vsub = tx >> 2;                    // 0..7
        int bsub = tx & 3;                     // 0..3
        if (tid < B_SZ) bmax[tid] = 0ull;

        unsigned long long acc[8][4];          // [v][b], each = (even-k, odd-k)
#pragma unroll
        for (int j = 0; j < 8; j++)
#pragma unroll
            for (int m = 0; m < 4; m++) acc[j][m] = 0ull;

        float pw[32], ph[8];
        // prefetch chunk kc=0: thread covers k=tk, v=tg+4j / b=tg+4j
#pragma unroll
        for (int j = 0; j < 32; j++)
            pw[j] = ldg_el(Wo + (size_t)(v0 + tg + 4 * j) * DHID + tk, pol);
#pragma unroll
        for (int j = 0; j < 8; j++)
            ph[j] = g_h[(tg + 4 * j) * DHID + tk];

        for (int kc = 0; kc < DHID; kc += 32) {
            __syncthreads();
#pragma unroll
            for (int j = 0; j < 32; j++) wo_s[(tg + 4 * j) * LSTR + tk] = pw[j];
#pragma unroll
            for (int j = 0; j < 8; j++)  h_s[(tg + 4 * j) * LSTR + tk] = ph[j];
            __syncthreads();
            if (kc + 32 < DHID) {
#pragma unroll
                for (int j = 0; j < 32; j++)
                    pw[j] = ldg_el(Wo + (size_t)(v0 + tg + 4 * j) * DHID
                                      + kc + 32 + tk, pol);
#pragma unroll
                for (int j = 0; j < 8; j++)
                    ph[j] = g_h[(tg + 4 * j) * DHID + kc + 32 + tk];
            }
            const float* wb = wo_s + (vg * 64 + vsub) * LSTR;
            const float* hb = h_s + (bg * 16 + bsub) * LSTR;
#pragma unroll
            for (int g = 0; g < 8; g++) {     // 4 k per group = 2 f32x2 pairs
                ulonglong2 wq[8];
#pragma unroll
                for (int j = 0; j < 8; j++)
                    wq[j] = *reinterpret_cast<const ulonglong2*>(
                        wb + j * 8 * LSTR + g * 4);
                ulonglong2 hq[4];
#pragma unroll
                for (int m = 0; m < 4; m++)
                    hq[m] = *reinterpret_cast<const ulonglong2*>(
                        hb + m * 4 * LSTR + g * 4);
#pragma unroll
                for (int j = 0; j < 8; j++)
#pragma unroll
                    for (int m = 0; m < 4; m++) {
                        ffma2(acc[j][m], wq[j].x, hq[m].x);
                        ffma2(acc[j][m], wq[j].y, hq[m].y);
                    }
            }
        }

        // stage results to smem: st[b][v] stride 132
        __syncthreads();
        float* st = sm;
#pragma unroll
        for (int j = 0; j < 8; j++) {
            int v = vg * 64 + vsub + 8 * j;
#pragma unroll
            for (int m = 0; m < 4; m++) {
                int b = bg * 16 + bsub + 4 * m;
                st[b * 132 + v] = fcollapse(acc[j][m]);
            }
        }
        __syncthreads();

        // coalesced write-out + argmax: thread handles 32 consecutive v of row b
        {
            int b = tid >> 2, q = tid & 3;
            int vbase = v0 + q * 32;
            const float* srow = st + b * 132 + q * 32;
            float best = -3.4e38f; int bi = 0;
            float vals[32];
#pragma unroll
            for (int i = 0; i < 32; i++) {
                float x = srow[i] + bo[vbase + i];
                vals[i] = x;
                if (x > best) { best = x; bi = vbase + i; }
            }
            float* orow = out_t + (size_t)b * VOCAB + vbase;
#pragma unroll
            for (int i = 0; i < 8; i++) {
                float4 v4 = make_float4(vals[4 * i], vals[4 * i + 1],
                                        vals[4 * i + 2], vals[4 * i + 3]);
                __stcs(reinterpret_cast<float4*>(orow + 4 * i), v4);
            }
            atomicMax(&bmax[b], packkey(best, bi));
        }
        __syncthreads();
        if (tid < B_SZ) atomicMax(&g_amax[tid], bmax[tid]);
        return;
    }

    if (bk < 298) {
        // ---- gh partial: tile 128o x 32b, K range [c*128, c*128+128) -------
        unsigned long long pol = mk_policy_el();
        int r = bk - 250;
        int c = r & 3, ot = r >> 2;
        int o0 = ot * 128, kc0 = c * 128;
        float* w_s = sm;              // [k][o] stride 129
        float* x_s = sm + 4128;       // [k][b] stride 33
        int tk = tid & 31, tg = tid >> 5;
        int tx = tid & 31, ty = tid >> 5;
        float acc[4][8] = {};
        float pw[32], ph[8];
#pragma unroll
        for (int j = 0; j < 32; j++)
            pw[j] = ldg_el(W_hh + (o0 + tg + 4 * j) * DHID + kc0 + tk, pol);
#pragma unroll
        for (int j = 0; j < 8; j++)
            ph[j] = g_h[(tg + 4 * j) * DHID + kc0 + tk];
        for (int kc = kc0; kc < kc0 + 128; kc += 32) {
            __syncthreads();
#pragma unroll
            for (int j = 0; j < 32; j++) w_s[tk * 129 + tg + 4 * j] = pw[j];
#pragma unroll
            for (int j = 0; j < 8; j++)  x_s[tk * 33 + tg + 4 * j] = ph[j];
            __syncthreads();
            if (kc + 32 < kc0 + 128) {
#pragma unroll
                for (int j = 0; j < 32; j++)
                    pw[j] = ldg_el(W_hh + (o0 + tg + 4 * j) * DHID + kc + 32 + tk, pol);
#pragma unroll
                for (int j = 0; j < 8; j++)
                    ph[j] = g_h[(tg + 4 * j) * DHID + kc + 32 + tk];
            }
#pragma unroll 4
            for (int k = 0; k < 32; k++) {
                const float* wr = &w_s[k * 129 + tx];
                float w0 = wr[0], w1 = wr[32], w2 = wr[64], w3 = wr[96];
                const float* hr = &x_s[k * 33 + ty * 8];
#pragma unroll
                for (int bj = 0; bj < 8; bj++) {
                    float hb = hr[bj];
                    acc[0][bj] = fmaf(w0, hb, acc[0][bj]);
                    acc[1][bj] = fmaf(w1, hb, acc[1][bj]);
                    acc[2][bj] = fmaf(w2, hb, acc[2][bj]);
                    acc[3][bj] = fmaf(w3, hb, acc[3][bj]);
                }
            }
        }
#pragma unroll
        for (int vi = 0; vi < 4; vi++)
#pragma unroll
            for (int bj = 0; bj < 8; bj++)
                g_ghp[(c * 3 * DHID + o0 + tx + vi * 32) * B_SZ + ty * 8 + bj] = acc[vi][bj];
        return;
    }

    // ---- attention for next step, one block per batch ----------------------
    {
        int b = bk - 298;
        float* h_sh  = sm;         // 512
        float* part  = sm + 512;   // 4*32
        float* hproj = sm + 640;   // 32
        float* sc    = sm + 672;   // 128
        float* red   = sm + 800;   // 2
        for (int i = tid; i < DHID; i += 128) h_sh[i] = g_h[b * DHID + i];
        __syncthreads();
        {   // hproj[a] = W1[a,0:512] @ h : 4 segments of 128
            int a = tid & 31, seg = tid >> 5;
            const float* w  = W1 + a * CATD + seg * 128;
            const float* hh = h_sh + seg * 128;
            float acc = 0.f;
#pragma unroll 8
            for (int k = 0; k < 128; k++) acc = fmaf(w[k], hh[k], acc);
            part[seg * 32 + a] = acc;
        }
        __syncthreads();
        if (tid < AHID)
            hproj[tid] = part[tid] + part[32 + tid] + part[64 + tid] + part[96 + tid];
        __syncthreads();
        {   // scores over S (one thread per s)
            int s = tid;
            const float* ep = g_enc_proj + (s * B_SZ + b) * AHID;
            float sv = b2[0];
#pragma unroll
            for (int a = 0; a < AHID; a++) {
                float t = ep[a] + hproj[a];
                sv = fmaf(W2[a], fmaxf(t, 0.f), sv);
            }
            sc[s] = sv;
        }
        __syncthreads();
        if (tid < 32) {
            float m = fmaxf(fmaxf(sc[tid], sc[tid + 32]), fmaxf(sc[tid + 64], sc[tid + 96]));
#pragma unroll
            for (int off = 16; off > 0; off >>= 1)
                m = fmaxf(m, __shfl_xor_sync(0xffffffffu, m, off));
            if (tid == 0) red[0] = m;
        }
        __syncthreads();
        sc[tid] = expf(sc[tid] - red[0]);
        __syncthreads();
        if (tid < 32) {
            float s4 = sc[tid] + sc[tid + 32] + sc[tid + 64] + sc[tid + 96];
#pragma unroll
            for (int off = 16; off > 0; off >>= 1)
                s4 += __shfl_xor_sync(0xffffffffu, s4, off);
            if (tid == 0) red[1] = 1.0f / s4;
        }
        __syncthreads();
        sc[tid] *= red[1];
        __syncthreads();
        {   // context: each thread 8 consecutive e
            float acc[8] = {};
            const float4* e4 = reinterpret_cast<const float4*>(enc);
#pragma unroll 4
            for (int s = 0; s < S_LEN; s++) {
                float a = sc[s];
                int base4 = ((s * B_SZ + b) * E2D + tid * 8) >> 2;
                float4 v0 = e4[base4], v1 = e4[base4 + 1];
                acc[0] = fmaf(a, v0.x, acc[0]); acc[1] = fmaf(a, v0.y, acc[1]);
                acc[2] = fmaf(a, v0.z, acc[2]); acc[3] = fmaf(a, v0.w, acc[3]);
                acc[4] = fmaf(a, v1.x, acc[4]); acc[5] = fmaf(a, v1.y, acc[5]);
                acc[6] = fmaf(a, v1.z, acc[6]); acc[7] = fmaf(a, v1.w, acc[7]);
            }
            float* dst = g_ctx + b * E2D + tid * 8;
#pragma unroll
            for (int j = 0; j < 8; j++) dst[j] = acc[j];
        }
    }
}

// ---------------- gi partial GEMM (x = [ctx | emb[argmax]]) -----------------
// grid 240 blocks (24 o-tiles of 64 x 10 K-splits), 128 threads
__global__ void __launch_bounds__(128) k_gigemm(const float* __restrict__ W_ih,
                                                const float* __restrict__ emb) {
    __shared__ __align__(16) float w_s[32 * 65];
    __shared__ float x_s[32 * 33];
    __shared__ int sh_id[B_SZ];
    int tid = threadIdx.x;
    unsigned long long pol = mk_policy_el();
    int ot = blockIdx.x % 24, sp = blockIdx.x / 24;
    int o0 = ot * 64, kc0 = sp * 128;
    int tk = tid & 31, tg = tid >> 5;
    if (tid < B_SZ) {
        unsigned long long p = g_amax[tid];
        sh_id[tid] = (int)(0x7FFFFFFFu - (unsigned int)(p & 0x7FFFFFFFull));
    }
    __syncthreads();
    int tx = tid & 31, ty = tid >> 5;
    bool is_ctx = (kc0 < E2D);
    float acc[2][8] = {};
    float pw[16], px[8];
#pragma unroll
    for (int j = 0; j < 16; j++)
        pw[j] = ldg_el(W_ih + (o0 + tg + 4 * j) * XDIM + kc0 + tk, pol);
#pragma unroll
    for (int j = 0; j < 8; j++) {
        int b = tg + 4 * j, kg = kc0 + tk;
        px[j] = is_ctx ? g_ctx[b * E2D + kg]
                       : emb[(size_t)sh_id[b] * EMBD + (kg - E2D)];
    }
    for (int kc = kc0; kc < kc0 + 128; kc += 32) {
        __syncthreads();
#pragma unroll
        for (int j = 0; j < 16; j++) w_s[tk * 65 + tg + 4 * j] = pw[j];
#pragma unroll
        for (int j = 0; j < 8; j++)  x_s[tk * 33 + tg + 4 * j] = px[j];
        __syncthreads();
        if (kc + 32 < kc0 + 128) {
#pragma unroll
            for (int j = 0; j < 16; j++)
                pw[j] = ldg_el(W_ih + (o0 + tg + 4 * j) * XDIM + kc + 32 + tk, pol);
#pragma unroll
            for (int j = 0; j < 8; j++) {
                int b = tg + 4 * j, kg = kc + 32 + tk;
                px[j] = is_ctx ? g_ctx[b * E2D + kg]
                               : emb[(size_t)sh_id[b] * EMBD + (kg - E2D)];
            }
        }
#pragma unroll 4
        for (int k = 0; k < 32; k++) {
            const float* wr = &w_s[k * 65 + tx];
            float w0 = wr[0], w1 = wr[32];
            const float* hr = &x_s[k * 33 + ty * 8];
#pragma unroll
            for (int bj = 0; bj < 8; bj++) {
                float hb = hr[bj];
                acc[0][bj] = fmaf(w0, hb, acc[0][bj]);
                acc[1][bj] = fmaf(w1, hb, acc[1][bj]);
            }
        }
    }
#pragma unroll
    for (int vi = 0; vi < 2; vi++)
#pragma unroll
        for (int bj = 0; bj < 8; bj++)
            g_gip[(sp * 3 * DHID + o0 + tx + vi * 32) * B_SZ + ty * 8 + bj] = acc[vi][bj];
}

// ---------------- GRU elementwise: sum partials, gates, h_new ---------------
__global__ void __launch_bounds__(128) k_gruelem(const float* __restrict__ b_ih,
                                                 const float* __restrict__ b_hh) {
    int i = blockIdx.x * blockDim.x + threadIdx.x;
    if (i >= B_SZ * DHID) return;
    int b = i & 31, d = i >> 5;
    float gr = 0.f, gz = 0.f, gn = 0.f;
#pragma unroll
    for (int sp = 0; sp < NSPI; sp++) {
        int base = (sp * 3 * DHID + d) * B_SZ + b;
        gr += g_gip[base];
        gz += g_gip[base + DHID * B_SZ];
        gn += g_gip[base + 2 * DHID * B_SZ];
    }
    float hr = 0.f, hz = 0.f, hn = 0.f;
#pragma unroll
    for (int c = 0; c < NSPH; c++) {
        int base = (c * 3 * DHID + d) * B_SZ + b;
        hr += g_ghp[base];
        hz += g_ghp[base + DHID * B_SZ];
        hn += g_ghp[base + 2 * DHID * B_SZ];
    }
    float gir = gr + hr + b_ih[d] + b_hh[d];
    float giz = gz + hz + b_ih[DHID + d] + b_hh[DHID + d];
    float gin = gn + b_ih[2 * DHID + d];
    float ghn = hn + b_hh[2 * DHID + d];
    float r = 1.f / (1.f + expf(-gir));
    float z = 1.f / (1.f + expf(-giz));
    float n = tanhf(fmaf(r, ghn, gin));
    float ho = g_h[b * DHID + d];
    g_h[b * DHID + d] = fmaf(z, ho - n, n);
    if (i < B_SZ) g_amax[i] = 0ull;   // reset before this step's logits atomics
}

// ---------------- launch ----------------------------------------------------
extern "C" void kernel_launch(void* const* d_in, const int* in_sizes, int n_in,
                              void* d_out, int out_size) {
    const float* enc   = (const float*)d_in[0];
    const int*   sos_p = (const int*)  d_in[2];
    const float* emb   = (const float*)d_in[3];
    const float* W1    = (const float*)d_in[4];
    const float* b1    = (const float*)d_in[5];
    const float* W2    = (const float*)d_in[6];
    const float* b2    = (const float*)d_in[7];
    const float* W_ih  = (const float*)d_in[8];
    const float* b_ih  = (const float*)d_in[9];
    const float* W_hh  = (const float*)d_in[10];
    const float* b_hh  = (const float*)d_in[11];
    const float* Wo    = (const float*)d_in[12];
    const float* bo    = (const float*)d_in[13];
    float* out = (float*)d_out;

    int T = out_size / (B_SZ * VOCAB);

    k_init<<<64, 256>>>(sos_p);
    k_encproj<<<S_LEN * B_SZ / 8, 256>>>(enc, W1, b1);
    // prologue: attn(0) + gh(0), no logits
    k_estep<<<330, 128>>>(enc, W1, W2, b2, W_hh, Wo, bo, nullptr);

    for (int t = 0; t < T; t++) {
        k_gigemm<<<240, 128>>>(W_ih, emb);
        k_gruelem<<<128, 128>>>(b_ih, b_hh);
        // logits(t) + attn(t+1) + gh(t+1)  (the t=T-1 extras are harmless)
        k_estep<<<330, 128>>>(enc, W1, W2, b2, W_hh, Wo, bo,
                              out + (size_t)t * B_SZ * VOCAB);
    }
}